// round 17
// baseline (speedup 1.0000x reference)
#include <cuda_runtime.h>
#include <cuda_bf16.h>

// Problem constants (B, H, W, SCALE) = (8, 384, 1280, 2)
#define BD   8
#define HD   384
#define WD   1280
#define LHD  (HD / 4)    // 96
#define LWD  (WD / 4)    // 320
#define NCELL (BD * LHD * LWD)  // 245760

#define NTHREADS 32
#define NBLOCKS  (NCELL / NTHREADS)   // 7680 single-warp blocks

typedef unsigned long long u64;

// ---- packed f32x2 primitives (sm_100+): per-lane RN, bit-identical to scalar
__device__ __forceinline__ u64 pk2(float lo, float hi) {
    u64 r; asm("mov.b64 %0, {%1, %2};" : "=l"(r) : "f"(lo), "f"(hi)); return r;
}
__device__ __forceinline__ void upk2(u64 v, float& lo, float& hi) {
    asm("mov.b64 {%0, %1}, %2;" : "=f"(lo), "=f"(hi) : "l"(v));
}
__device__ __forceinline__ u64 fma2(u64 a, u64 b, u64 c) {
    u64 d; asm("fma.rn.f32x2 %0, %1, %2, %3;" : "=l"(d) : "l"(a), "l"(b), "l"(c)); return d;
}
__device__ __forceinline__ u64 mul2(u64 a, u64 b) {
    u64 d; asm("mul.rn.f32x2 %0, %1, %2;" : "=l"(d) : "l"(a), "l"(b)); return d;
}
__device__ __forceinline__ u64 add2(u64 a, u64 b) {
    u64 d; asm("add.rn.f32x2 %0, %1, %2;" : "=l"(d) : "l"(a), "l"(b)); return d;
}

// ---------------------------------------------------------------------------
// Lean packed two-angle sincos, CLASS-REP output ((s,c) up to a global sign,
// erased bit-exactly by downstream |e|). Erratic abs err ~3e-9 (proven
// metric-invisible, R16):
//   sin(rh+rl) = [rh + T exact] + rl*ch            (ch ~ cos(rh))
//   cos(rh+rl) = [1 - zh/2 exact] + z^2*pc - ze/2 - (rl*rh)*(1 + z*h1)
// where ze = rh^2 - fl(rh^2) exact, u = z*h1 ~ sin(rh)/rh - 1.
// ---------------------------------------------------------------------------
__device__ __forceinline__ void ffsincos2(float xa, float xb,
                                          float& sA, float& cA,
                                          float& sB, float& cB)
{
    const u64 K_INV  = pk2(0.636619772367581343f, 0.636619772367581343f);
    const u64 K_MAG  = pk2(12582912.0f, 12582912.0f);
    const u64 K_NMAG = pk2(-12582912.0f, -12582912.0f);
    const u64 K_NPH  = pk2(-1.5703125f, -1.5703125f);
    const u64 K_NPM  = pk2(-4.83751297e-4f, -4.83751297e-4f);
    const u64 K_NPL  = pk2(-7.54978995e-8f, -7.54978995e-8f);
    const u64 K_N1   = pk2(-1.0f, -1.0f);
    const u64 K_1    = pk2(1.0f, 1.0f);
    const u64 K_HLF  = pk2(0.5f, 0.5f);

    u64 x = pk2(xa, xb);
    u64 t = fma2(x, K_INV, K_MAG);
    float tlo, thi; upk2(t, tlo, thi);
    int pa = __float_as_int(tlo);                // low bits == k
    int pb = __float_as_int(thi);
    u64 fk  = add2(t, K_NMAG);                   // exact
    u64 a   = fma2(fk, K_NPH, x);                // exact (Sterbenz)
    u64 p2n = mul2(fk, K_NPM);                   // exact, == -fk*PM
    // Fast2Sum(a, p2n): r = rh + e1 (+ fk*PL tail)
    u64 rh = add2(a, p2n);
    u64 zb = fma2(a, K_N1, rh);                  // rh - a
    u64 e1 = fma2(zb, K_N1, p2n);                // p2n - zb
    u64 rl = fma2(fk, K_NPL, e1);                // |rl| <= ~3.2e-7

    u64 zh  = mul2(rh, rh);
    u64 zhn = mul2(zh, K_N1);
    u64 ze  = fma2(rh, rh, zhn);                 // rh^2 - zh, exact residual

    // exact split of (1 - zh/2)
    u64 hm = mul2(zh, K_HLF);                    // zh/2, exact
    u64 ch = fma2(hm, K_N1, K_1);                // fl(1 - zh/2)
    u64 t1 = fma2(ch, K_N1, K_1);                // 1 - ch (exact, Sterbenz)
    u64 cl = fma2(hm, K_N1, t1);                 // exact lo part

    // ---- sin ----
    const u64 KS4  = pk2( 2.75573137070700677e-6f,   2.75573137070700677e-6f);
    const u64 KS3  = pk2(-1.98412698298579493e-4f,  -1.98412698298579493e-4f);
    const u64 KS2  = pk2( 8.33333376795053482e-3f,   8.33333376795053482e-3f);
    const u64 KS1  = pk2(-0.166666671633720398f,    -0.166666671633720398f);

    u64 h1 = fma2(zh, KS4, KS3);
    h1 = fma2(zh, h1, KS2);
    h1 = fma2(zh, h1, KS1);
    u64 u  = mul2(zh, h1);                       // ~ sin(rh)/rh - 1
    u64 T  = mul2(rh, u);
    u64 sh = add2(rh, T);                        // Fast2Sum: |rh| >= |T|
    u64 sb = fma2(rh, K_N1, sh);                 // sh - rh
    u64 se = fma2(sb, K_N1, T);                  // exact tail of rh+T
    u64 rlc = mul2(rl, ch);                      // rl*cos(rh) to ~1e-14
    u64 stl = add2(se, rlc);
    u64 spre = add2(sh, stl);

    // ---- cos ----
    const u64 KC4  = pk2(-2.75573143513906633e-7f,  -2.75573143513906633e-7f);
    const u64 KC3  = pk2( 2.48015872894767294e-5f,   2.48015872894767294e-5f);
    const u64 KC2  = pk2(-1.38888892255723476e-3f,  -1.38888892255723476e-3f);
    const u64 KC1  = pk2( 4.16666679084301e-2f,      4.16666679084301e-2f);

    u64 pc = fma2(zh, KC4, KC3);
    pc = fma2(zh, pc, KC2);
    pc = fma2(zh, pc, KC1);
    u64 z2 = mul2(zh, zh);
    u64 co = fma2(z2, pc, cl);
    u64 zeh = mul2(ze, K_HLF);
    co = fma2(zeh, K_N1, co);                    // - ze/2
    u64 sfac = add2(K_1, u);                     // ~ sin(rh)/rh
    u64 rr  = mul2(rl, rh);
    u64 rrc = mul2(rr, sfac);
    co = fma2(rrc, K_N1, co);                    // - rl*sin(rh)
    u64 cpre = add2(ch, co);

    float spA, spB, cpA, cpB;
    upk2(spre, spA, spB);
    upk2(cpre, cpA, cpB);

    // class-rep quadrant fix: k odd -> (s,c) = (c, -s); k even -> (s, c)
    {
        const bool odd = (pa & 1);
        float s0 = odd ? cpA : spA;
        float cr = odd ? spA : cpA;
        cA = __int_as_float(__float_as_int(cr) ^ (pa << 31));
        sA = s0;
    }
    {
        const bool odd = (pb & 1);
        float s0 = odd ? cpB : spB;
        float cr = odd ? spB : cpB;
        cB = __int_as_float(__float_as_int(cr) ^ (pb << 31));
        sB = s0;
    }
}

__device__ __forceinline__ float fexp(float x) { return __expf(x); }

// e = fadd(fmul(s, c1), fmul(m1, c0)) -- |e| invariant under the class-rep
// global sign. log difference via log2*ln2 (outputs non-amplification-
// critical, R7-R16 evidence).
__device__ __forceinline__ float log_ratio(float s3, float c0,
                                           float m1, float c1, float c2)
{
    const float pm = 1e-6f;
    const float t  = __fmul_rn(m1, c0);
    float e1 = __fadd_rn(__fmul_rn(s3, c1), t);
    float e2 = __fadd_rn(__fmul_rn(s3, c2), t);
    float la = __log2f(fmaxf(fabsf(e1), pm));
    float lb = __log2f(fmaxf(fabsf(e2), pm));
    float v  = __fmul_rn(__fsub_rn(la, lb), 0.69314718055994530942f);
    return fminf(fmaxf(v, -10.0f), 10.0f);
}

// Occupancy ceiling raised 16 -> 20 CTAs/SM (reg cap 102 >= current 99):
// R16 showed achieved occ pinned at 86% of the old self-imposed 16-CTA
// ceiling with issue at 61% -- residency, not fma slots, is binding.
__global__ __launch_bounds__(NTHREADS, 20)
void sno_kernel(const float* __restrict__ depth,
                const float* __restrict__ ang,
                const float* __restrict__ intr,
                float* __restrict__ out)
{
    const int tid = blockIdx.x * NTHREADS + threadIdx.x;

    int cx = tid % LWD;
    int t  = tid / LWD;
    int cy = t % LHD;
    int b  = t / LHD;

    const float fx = intr[b * 9 + 0];
    const float bx = intr[b * 9 + 2];
    const float fy = intr[b * 9 + 4];
    const float by = intr[b * 9 + 5];

    const int y0 = cy * 4;   // block top row  (== yy0 - 2)
    const int x0 = cx * 4;   // block left col (== xx0 - 2)

    const float* __restrict__ angh = ang + (size_t)(b * 2 + 0) * HD * WD;
    const float* __restrict__ angv = ang + (size_t)(b * 2 + 1) * HD * WD;

    // Hoisted geometry (bit-exact reuse: b2[c] == -tx[c+1], v2[r] == -ty[r+1])
    float tx[4], ty[4], a1[4], u1[4];
    #pragma unroll
    for (int i = 0; i < 4; ++i) {
        const float xf = (float)(x0 + i);
        const float yf = (float)(y0 + i);
        tx[i] = __fdiv_rn(__fsub_rn(xf, bx), fx);
        ty[i] = __fdiv_rn(__fsub_rn(yf, by), fy);
        a1[i] = __fadd_rn(__fmul_rn(ty[i], ty[i]), 1.0f);
        u1[i] = __fadd_rn(__fmul_rn(tx[i], tx[i]), 1.0f);
    }

    float lh[4][3];
    float lv[3][4];

    // ---- horizontal: 12 angles, 6 packed sincos ----
    {
        float hv[12];
        #pragma unroll
        for (int r = 0; r < 4; ++r) {
            const float4 hr = *reinterpret_cast<const float4*>(
                angh + (size_t)(y0 + r) * WD + x0);
            hv[3 * r + 0] = hr.x;
            hv[3 * r + 1] = hr.y;
            hv[3 * r + 2] = hr.z;
        }
        #pragma unroll
        for (int i = 0; i < 6; ++i) {
            const int iA = 2 * i, iB = 2 * i + 1;
            const int rA = iA / 3, cA = iA % 3;
            const int rB = iB / 3, cB = iB % 3;
            float sA, coA, sB, coB;
            ffsincos2(hv[iA], hv[iB], sA, coA, sB, coB);
            lh[rA][cA] = log_ratio(sA, coA, a1[rA], -tx[cA], -tx[cA + 1]);
            lh[rB][cB] = log_ratio(sB, coB, a1[rB], -tx[cB], -tx[cB + 1]);
        }
    }

    // ---- vertical: 12 angles, 6 packed sincos ----
    #pragma unroll
    for (int r = 0; r < 3; ++r) {
        const float4 vr = *reinterpret_cast<const float4*>(
            angv + (size_t)(y0 + r) * WD + x0);
        float sA, coA, sB, coB;
        ffsincos2(vr.x, vr.y, sA, coA, sB, coB);
        lv[r][0] = log_ratio(sA, coA, u1[0], -ty[r], -ty[r + 1]);
        lv[r][1] = log_ratio(sB, coB, u1[1], -ty[r], -ty[r + 1]);
        ffsincos2(vr.z, vr.w, sA, coA, sB, coB);
        lv[r][2] = log_ratio(sA, coA, u1[2], -ty[r], -ty[r + 1]);
        lv[r][3] = log_ratio(sB, coB, u1[3], -ty[r], -ty[r + 1]);
    }

    // d[row][col]: row = mm+2, col = nn+2  -> pixel (y0+row, x0+col)
    float d[4][4];
    d[2][2] = __fmul_rn(__log2f(depth[tid]), 0.69314718055994530942f);

    #pragma unroll
    for (int m = 0; m < 4; ++m) {
        #pragma unroll
        for (int n = 0; n < 4; ++n) {
            if (m == 0 && n == 0) continue;
            const int mm = (m & 1) ? -((m + 1) >> 1) : (m >> 1);
            const int nn = (n & 1) ? -((n + 1) >> 1) : (n >> 1);

            int lx1 = 0, ly1 = 0, ch1 = 0, dx1 = 0, dy1 = 0;
            int lx2 = 0, ly2 = 0, ch2 = 0, dx2 = 0, dy2 = 0;
            float s1 = 0.0f, s2 = 0.0f;
            const bool has1 = (nn != 0);
            const bool has2 = (mm != 0);
            if (nn < 0)      { lx1 = nn;     ly1 = mm; ch1 = 0; dx1 = nn + 1; dy1 = mm;     s1 = -1.0f; }
            else if (nn > 0) { lx1 = nn - 1; ly1 = mm; ch1 = 0; dx1 = nn - 1; dy1 = mm;     s1 =  1.0f; }
            if (mm > 0)      { lx2 = nn; ly2 = mm - 1; ch2 = 1; dx2 = nn;     dy2 = mm - 1; s2 =  1.0f; }
            else if (mm < 0) { lx2 = nn; ly2 = mm;     ch2 = 1; dx2 = nn;     dy2 = mm + 1; s2 = -1.0f; }
            if (!has1) { lx1 = lx2; ly1 = ly2; ch1 = ch2; dx1 = dx2; dy1 = dy2; s1 = s2; }
            if (!has2) { lx2 = lx1; ly2 = ly1; ch2 = ch1; dx2 = dx1; dy2 = dy1; s2 = s1; }

            const float l1 = (ch1 == 0) ? lh[ly1 + 2][lx1 + 2] : lv[ly1 + 2][lx1 + 2];
            const float l2 = (ch2 == 0) ? lh[ly2 + 2][lx2 + 2] : lv[ly2 + 2][lx2 + 2];

            float acc = __fadd_rn(d[dy1 + 2][dx1 + 2], __fmul_rn(s1, l1));
            acc = __fadd_rn(acc, d[dy2 + 2][dx2 + 2]);
            acc = __fadd_rn(acc, __fmul_rn(s2, l2));
            d[mm + 2][nn + 2] = __fmul_rn(acc, 0.5f);
        }
    }

    #pragma unroll
    for (int r = 0; r < 4; ++r) {
        const int y = y0 + r;
        float4 o;
        o.x = fexp(d[r][0]);
        o.y = fexp(d[r][1]);
        o.z = fexp(d[r][2]);
        o.w = fexp(d[r][3]);
        *reinterpret_cast<float4*>(&out[((size_t)b * HD + y) * WD + x0]) = o;
    }
}

extern "C" void kernel_launch(void* const* d_in, const int* in_sizes, int n_in,
                              void* d_out, int out_size)
{
    const float* depth = (const float*)d_in[0];
    const float* ang   = (const float*)d_in[1];
    const float* intr  = (const float*)d_in[2];
    float* out = (float*)d_out;

    sno_kernel<<<NBLOCKS, NTHREADS>>>(depth, ang, intr, out);
}